// round 1
// baseline (speedup 1.0000x reference)
#include <cuda_runtime.h>

// LSTM seq2seq: B=65536, H=64, IN=9, enc 7 steps, dec 10 steps + FC(64->9).
// Thread-per-batch-element. Weights in SMEM (broadcast LDS.128), state packed
// into f32x2 register pairs, math via Blackwell packed fma.rn.f32x2.

#define BTOT    65536
#define H       64
#define IN      9
#define SRCLEN  7
#define PREDLEN 10
#define G4      256      // 4*H gate rows
#define WSTR    76       // padded row: [x:9][bias:1][h:64][pad:2]
#define NPAIR   38       // WSTR/2
#define TPB     256

typedef unsigned long long ull;

__device__ __forceinline__ ull pack2(float lo, float hi) {
    ull r; asm("mov.b64 %0, {%1, %2};" : "=l"(r) : "f"(lo), "f"(hi)); return r;
}
__device__ __forceinline__ void unpack2(ull p, float &lo, float &hi) {
    asm("mov.b64 {%0, %1}, %2;" : "=f"(lo), "=f"(hi) : "l"(p));
}
__device__ __forceinline__ void ffma2(ull &acc, ull a, ull b) {
    asm("fma.rn.f32x2 %0, %1, %2, %0;" : "+l"(acc) : "l"(a), "l"(b));
}
__device__ __forceinline__ float psum(ull p) {
    float lo, hi; unpack2(p, lo, hi); return lo + hi;
}

__device__ __forceinline__ float fast_sigmoid(float x) {
    float e = __expf(-x);
    return __fdividef(1.0f, 1.0f + e);
}
__device__ __forceinline__ float fast_tanh(float x) {
    // clamp to avoid inf/inf NaN for extreme inputs (tanh saturates anyway)
    x = fminf(fmaxf(x, -15.0f), 15.0f);
    float e = __expf(-2.0f * x);
    return __fdividef(1.0f - e, 1.0f + e);
}

// smem layout (floats)
#define OFF_W    0
#define OFF_C    (G4 * WSTR)                 // 19456
#define OFF_HB   (OFF_C + H * TPB)           // +16384
#define OFF_FCW  (OFF_HB + H * TPB)          // +16384
#define OFF_FCB  (OFF_FCW + IN * H)          // +576
#define SMEM_FLOATS (OFF_FCB + 16)
#define SMEM_BYTES  (SMEM_FLOATS * 4)

__device__ __forceinline__ void lstm_step(const float* __restrict__ w,
                                          float* __restrict__ cbuf,
                                          float* __restrict__ hb,
                                          ull (&s2)[NPAIR], int tid)
{
    const float* wr = w;
    #pragma unroll 1
    for (int j = 0; j < H; j++) {
        const float* w0 = wr;
        const float* w1 = wr + 64  * WSTR;
        const float* w2 = wr + 128 * WSTR;
        const float* w3 = wr + 192 * WSTR;
        ull a0 = 0, a1 = 0, a2 = 0, a3 = 0;
        #pragma unroll
        for (int p = 0; p < NPAIR; p += 2) {
            ulonglong2 q0 = *(const ulonglong2*)(w0 + 2 * p);
            ffma2(a0, s2[p], q0.x); ffma2(a0, s2[p + 1], q0.y);
            ulonglong2 q1 = *(const ulonglong2*)(w1 + 2 * p);
            ffma2(a1, s2[p], q1.x); ffma2(a1, s2[p + 1], q1.y);
            ulonglong2 q2 = *(const ulonglong2*)(w2 + 2 * p);
            ffma2(a2, s2[p], q2.x); ffma2(a2, s2[p + 1], q2.y);
            ulonglong2 q3 = *(const ulonglong2*)(w3 + 2 * p);
            ffma2(a3, s2[p], q3.x); ffma2(a3, s2[p + 1], q3.y);
        }
        float gi = psum(a0), gf = psum(a1), gg = psum(a2), go = psum(a3);
        float ig = fast_sigmoid(gi);
        float fg = fast_sigmoid(gf);
        float g  = fast_tanh(gg);
        float og = fast_sigmoid(go);
        float c  = cbuf[j * TPB + tid];
        c = fg * c + ig * g;
        cbuf[j * TPB + tid] = c;
        float hn = og * fast_tanh(c);
        // stage h into pair layout: [pair][tid][2]
        hb[(((j >> 1) * TPB + tid) << 1) | (j & 1)] = hn;
        wr += WSTR;
    }
    // reload new h into packed register pairs (constant-indexed)
    #pragma unroll
    for (int p = 0; p < H / 2; p++) {
        s2[5 + p] = *(const ull*)(hb + ((p * TPB + tid) << 1));
    }
}

__global__ void __launch_bounds__(TPB, 1)
lstm_seq2seq_kernel(const float* __restrict__ src,
                    const float* __restrict__ eWih, const float* __restrict__ eWhh,
                    const float* __restrict__ eb,
                    const float* __restrict__ dWih, const float* __restrict__ dWhh,
                    const float* __restrict__ db,
                    const float* __restrict__ fcW,  const float* __restrict__ fcbg,
                    float* __restrict__ out)
{
    extern __shared__ float smem[];
    float* w    = smem + OFF_W;
    float* cbuf = smem + OFF_C;
    float* hb   = smem + OFF_HB;
    float* fcw  = smem + OFF_FCW;
    float* fcb  = smem + OFF_FCB;

    const int tid   = threadIdx.x;
    const int batch = blockIdx.x * TPB + tid;

    // ---- load encoder weights into fused row layout ----
    {
        const int r = tid;  // one gate-row per thread (G4 == TPB)
        float* wr = w + r * WSTR;
        #pragma unroll
        for (int k = 0; k < IN; k++) wr[k] = eWih[r * IN + k];
        wr[9] = eb[r];
        #pragma unroll
        for (int k = 0; k < H; k++) wr[10 + k] = eWhh[r * H + k];
        wr[74] = 0.0f; wr[75] = 0.0f;
    }
    // init c = 0
    #pragma unroll 1
    for (int j = 0; j < H; j++) cbuf[j * TPB + tid] = 0.0f;
    __syncthreads();

    // packed state: pairs 0..4 = [x0..x8, 1], pairs 5..36 = h, pair 37 = 0
    ull s2[NPAIR];
    #pragma unroll
    for (int p = 0; p < NPAIR; p++) s2[p] = 0ull;   // h starts at 0

    const float* xp = src + (size_t)batch * (SRCLEN * IN);

    // ---- encoder ----
    #pragma unroll 1
    for (int t = 0; t < SRCLEN; t++) {
        float xv[IN];
        #pragma unroll
        for (int k = 0; k < IN; k++) xv[k] = xp[t * IN + k];
        s2[0] = pack2(xv[0], xv[1]);
        s2[1] = pack2(xv[2], xv[3]);
        s2[2] = pack2(xv[4], xv[5]);
        s2[3] = pack2(xv[6], xv[7]);
        s2[4] = pack2(xv[8], 1.0f);
        lstm_step(w, cbuf, hb, s2, tid);
    }

    // ---- swap in decoder weights ----
    __syncthreads();   // everyone done reading encoder weights
    {
        const int r = tid;
        float* wr = w + r * WSTR;
        #pragma unroll
        for (int k = 0; k < IN; k++) wr[k] = dWih[r * IN + k];
        wr[9] = db[r];
        #pragma unroll
        for (int k = 0; k < H; k++) wr[10 + k] = dWhh[r * H + k];
        wr[74] = 0.0f; wr[75] = 0.0f;
    }
    for (int idx = tid; idx < IN * H; idx += TPB) fcw[idx] = fcW[idx];
    if (tid < IN) fcb[tid] = fcbg[tid];
    __syncthreads();

    // decoder first input = src[:, -1, :] — already resident in s2[0..4]
    float* outp = out + (size_t)batch * (PREDLEN * IN);

    // ---- decoder ----
    #pragma unroll 1
    for (int t = 0; t < PREDLEN; t++) {
        lstm_step(w, cbuf, hb, s2, tid);
        float pr[IN];
        #pragma unroll
        for (int m = 0; m < IN; m++) {
            ull acc = 0;
            const float* fr = fcw + m * H;
            #pragma unroll
            for (int p = 0; p < H / 2; p += 2) {
                ulonglong2 q = *(const ulonglong2*)(fr + 2 * p);
                ffma2(acc, s2[5 + p],     q.x);
                ffma2(acc, s2[5 + p + 1], q.y);
            }
            pr[m] = psum(acc) + fcb[m];
            outp[t * IN + m] = pr[m];
        }
        s2[0] = pack2(pr[0], pr[1]);
        s2[1] = pack2(pr[2], pr[3]);
        s2[2] = pack2(pr[4], pr[5]);
        s2[3] = pack2(pr[6], pr[7]);
        s2[4] = pack2(pr[8], 1.0f);
    }
}

extern "C" void kernel_launch(void* const* d_in, const int* in_sizes, int n_in,
                              void* d_out, int out_size)
{
    const float* src  = (const float*)d_in[0];
    const float* eWih = (const float*)d_in[1];
    const float* eWhh = (const float*)d_in[2];
    const float* eb   = (const float*)d_in[3];
    const float* dWih = (const float*)d_in[4];
    const float* dWhh = (const float*)d_in[5];
    const float* db   = (const float*)d_in[6];
    const float* fcW  = (const float*)d_in[7];
    const float* fcb  = (const float*)d_in[8];
    float* out = (float*)d_out;

    cudaFuncSetAttribute(lstm_seq2seq_kernel,
                         cudaFuncAttributeMaxDynamicSharedMemorySize, SMEM_BYTES);

    lstm_seq2seq_kernel<<<BTOT / TPB, TPB, SMEM_BYTES>>>(
        src, eWih, eWhh, eb, dWih, dWhh, db, fcW, fcb, out);
}

// round 3
// speedup vs baseline: 1.2881x; 1.2881x over previous
#include <cuda_runtime.h>

// LSTM seq2seq: B=65536, H=64, IN=9, enc 7 steps, dec 10 steps + FC(64->9).
// R=2 batch elements per thread: each broadcast weight load (LDS.128) feeds
// 4 packed fma.rn.f32x2 -> fma-pipe-bound instead of smem-crossbar-bound.

#define BTOT    65536
#define H       64
#define IN      9
#define SRCLEN  7
#define PREDLEN 10
#define G4      256      // 4*H gate rows
#define WSTR    76       // padded row: [x:9][bias:1][h:64][pad:2] (19 x 16B)
#define NPAIR   38       // WSTR/2
#define NCHUNK  19       // WSTR/4 (16B chunks)
#define TPB     128
#define EPB     256      // elements per block (R=2)

typedef unsigned long long ull;

__device__ __forceinline__ ull pack2(float lo, float hi) {
    ull r; asm("mov.b64 %0, {%1, %2};" : "=l"(r) : "f"(lo), "f"(hi)); return r;
}
__device__ __forceinline__ void unpack2(ull p, float &lo, float &hi) {
    asm("mov.b64 {%0, %1}, %2;" : "=f"(lo), "=f"(hi) : "l"(p));
}
__device__ __forceinline__ void ffma2(ull &acc, ull a, ull b) {
    asm("fma.rn.f32x2 %0, %1, %2, %0;" : "+l"(acc) : "l"(a), "l"(b));
}
__device__ __forceinline__ float psum(ull p) {
    float lo, hi; unpack2(p, lo, hi); return lo + hi;
}

__device__ __forceinline__ float fast_tanh(float x) {
    float y; asm("tanh.approx.f32 %0, %1;" : "=f"(y) : "f"(x)); return y;
}
__device__ __forceinline__ float fast_sigmoid(float x) {
    return fmaf(0.5f, fast_tanh(0.5f * x), 0.5f);
}

// smem layout (floats)
#define OFF_W    0
#define OFF_C    (G4 * WSTR)                 // 19456
#define OFF_HB   (OFF_C + H * EPB)           // +16384
#define OFF_FCW  (OFF_HB + H * EPB)          // +16384
#define OFF_FCB  (OFF_FCW + IN * H)          // +576
#define SMEM_FLOATS (OFF_FCB + 16)
#define SMEM_BYTES  (SMEM_FLOATS * 4)        // 211,264 B

__device__ __forceinline__ void lstm_step(const float* __restrict__ w,
                                          float* __restrict__ cbuf,
                                          float* __restrict__ hb,
                                          ull (&sA)[NPAIR], ull (&sB)[NPAIR],
                                          int tid)
{
    #pragma unroll 1
    for (int j = 0; j < H; j++) {
        const float* r0 = w + j * WSTR;
        const float* r1 = r0 + 64  * WSTR;
        const float* r2 = r0 + 128 * WSTR;
        const float* r3 = r0 + 192 * WSTR;
        ull a0A = 0, a1A = 0, a2A = 0, a3A = 0;
        ull a0B = 0, a1B = 0, a2B = 0, a3B = 0;
        #pragma unroll
        for (int p = 0; p < NCHUNK; p++) {
            ulonglong2 q0 = *(const ulonglong2*)(r0 + 4 * p);
            ffma2(a0A, sA[2*p], q0.x); ffma2(a0A, sA[2*p+1], q0.y);
            ffma2(a0B, sB[2*p], q0.x); ffma2(a0B, sB[2*p+1], q0.y);
            ulonglong2 q1 = *(const ulonglong2*)(r1 + 4 * p);
            ffma2(a1A, sA[2*p], q1.x); ffma2(a1A, sA[2*p+1], q1.y);
            ffma2(a1B, sB[2*p], q1.x); ffma2(a1B, sB[2*p+1], q1.y);
            ulonglong2 q2 = *(const ulonglong2*)(r2 + 4 * p);
            ffma2(a2A, sA[2*p], q2.x); ffma2(a2A, sA[2*p+1], q2.y);
            ffma2(a2B, sB[2*p], q2.x); ffma2(a2B, sB[2*p+1], q2.y);
            ulonglong2 q3 = *(const ulonglong2*)(r3 + 4 * p);
            ffma2(a3A, sA[2*p], q3.x); ffma2(a3A, sA[2*p+1], q3.y);
            ffma2(a3B, sB[2*p], q3.x); ffma2(a3B, sB[2*p+1], q3.y);
        }
        // element A
        {
            float ig = fast_sigmoid(psum(a0A));
            float fg = fast_sigmoid(psum(a1A));
            float g  = fast_tanh(psum(a2A));
            float og = fast_sigmoid(psum(a3A));
            float c  = cbuf[j * EPB + tid];
            c = fg * c + ig * g;
            cbuf[j * EPB + tid] = c;
            float hn = og * fast_tanh(c);
            hb[(((j >> 1) * EPB + tid) << 1) | (j & 1)] = hn;
        }
        // element B
        {
            float ig = fast_sigmoid(psum(a0B));
            float fg = fast_sigmoid(psum(a1B));
            float g  = fast_tanh(psum(a2B));
            float og = fast_sigmoid(psum(a3B));
            float c  = cbuf[j * EPB + tid + TPB];
            c = fg * c + ig * g;
            cbuf[j * EPB + tid + TPB] = c;
            float hn = og * fast_tanh(c);
            hb[(((j >> 1) * EPB + tid + TPB) << 1) | (j & 1)] = hn;
        }
    }
    // reload new h into packed register pairs (constant-indexed)
    #pragma unroll
    for (int p = 0; p < H / 2; p++) {
        sA[5 + p] = *(const ull*)(hb + ((p * EPB + tid) << 1));
        sB[5 + p] = *(const ull*)(hb + ((p * EPB + tid + TPB) << 1));
    }
}

__global__ void __launch_bounds__(TPB, 1)
lstm_seq2seq_kernel(const float* __restrict__ src,
                    const float* __restrict__ eWih, const float* __restrict__ eWhh,
                    const float* __restrict__ eb,
                    const float* __restrict__ dWih, const float* __restrict__ dWhh,
                    const float* __restrict__ db,
                    const float* __restrict__ fcW,  const float* __restrict__ fcbg,
                    float* __restrict__ out)
{
    extern __shared__ float smem[];
    float* w    = smem + OFF_W;
    float* cbuf = smem + OFF_C;
    float* hb   = smem + OFF_HB;
    float* fcw  = smem + OFF_FCW;
    float* fcb  = smem + OFF_FCB;

    const int tid = threadIdx.x;
    const int eA  = blockIdx.x * EPB + tid;        // element A
    const int eB  = eA + TPB;                      // element B

    // ---- load encoder weights into fused row layout (2 rows per thread) ----
    #pragma unroll
    for (int rr = 0; rr < 2; rr++) {
        const int r = tid + rr * TPB;
        float* wr = w + r * WSTR;
        #pragma unroll
        for (int k = 0; k < IN; k++) wr[k] = eWih[r * IN + k];
        wr[9] = eb[r];
        #pragma unroll
        for (int k = 0; k < H; k++) wr[10 + k] = eWhh[r * H + k];
        wr[74] = 0.0f; wr[75] = 0.0f;
    }
    // init c = 0
    #pragma unroll 1
    for (int j = 0; j < H; j++) {
        cbuf[j * EPB + tid] = 0.0f;
        cbuf[j * EPB + tid + TPB] = 0.0f;
    }
    __syncthreads();

    // packed state: pairs 0..4 = [x0..x8, 1], pairs 5..36 = h, pair 37 = 0
    ull sA[NPAIR], sB[NPAIR];
    #pragma unroll
    for (int p = 0; p < NPAIR; p++) { sA[p] = 0ull; sB[p] = 0ull; }

    const float* xpA = src + (size_t)eA * (SRCLEN * IN);
    const float* xpB = src + (size_t)eB * (SRCLEN * IN);

    // ---- encoder ----
    #pragma unroll 1
    for (int t = 0; t < SRCLEN; t++) {
        float xa[IN], xb[IN];
        #pragma unroll
        for (int k = 0; k < IN; k++) { xa[k] = xpA[t * IN + k]; xb[k] = xpB[t * IN + k]; }
        sA[0] = pack2(xa[0], xa[1]); sA[1] = pack2(xa[2], xa[3]);
        sA[2] = pack2(xa[4], xa[5]); sA[3] = pack2(xa[6], xa[7]);
        sA[4] = pack2(xa[8], 1.0f);
        sB[0] = pack2(xb[0], xb[1]); sB[1] = pack2(xb[2], xb[3]);
        sB[2] = pack2(xb[4], xb[5]); sB[3] = pack2(xb[6], xb[7]);
        sB[4] = pack2(xb[8], 1.0f);
        lstm_step(w, cbuf, hb, sA, sB, tid);
    }

    // ---- swap in decoder weights ----
    __syncthreads();
    #pragma unroll
    for (int rr = 0; rr < 2; rr++) {
        const int r = tid + rr * TPB;
        float* wr = w + r * WSTR;
        #pragma unroll
        for (int k = 0; k < IN; k++) wr[k] = dWih[r * IN + k];
        wr[9] = db[r];
        #pragma unroll
        for (int k = 0; k < H; k++) wr[10 + k] = dWhh[r * H + k];
        wr[74] = 0.0f; wr[75] = 0.0f;
    }
    for (int idx = tid; idx < IN * H; idx += TPB) fcw[idx] = fcW[idx];
    if (tid < IN) fcb[tid] = fcbg[tid];
    __syncthreads();

    // decoder first input = src[:, -1, :] — already resident in sA/sB[0..4]
    float* outA = out + (size_t)eA * (PREDLEN * IN);
    float* outB = out + (size_t)eB * (PREDLEN * IN);

    // ---- decoder ----
    #pragma unroll 1
    for (int t = 0; t < PREDLEN; t++) {
        lstm_step(w, cbuf, hb, sA, sB, tid);
        float prA[IN], prB[IN];
        #pragma unroll
        for (int m = 0; m < IN; m++) {
            ull accA = 0, accB = 0;
            const float* fr = fcw + m * H;
            #pragma unroll
            for (int p = 0; p < 16; p++) {     // 16 chunks of 16B over 64 floats
                ulonglong2 q = *(const ulonglong2*)(fr + 4 * p);
                ffma2(accA, sA[5 + 2*p], q.x); ffma2(accA, sA[5 + 2*p + 1], q.y);
                ffma2(accB, sB[5 + 2*p], q.x); ffma2(accB, sB[5 + 2*p + 1], q.y);
            }
            prA[m] = psum(accA) + fcb[m];
            prB[m] = psum(accB) + fcb[m];
            outA[t * IN + m] = prA[m];
            outB[t * IN + m] = prB[m];
        }
        sA[0] = pack2(prA[0], prA[1]); sA[1] = pack2(prA[2], prA[3]);
        sA[2] = pack2(prA[4], prA[5]); sA[3] = pack2(prA[6], prA[7]);
        sA[4] = pack2(prA[8], 1.0f);
        sB[0] = pack2(prB[0], prB[1]); sB[1] = pack2(prB[2], prB[3]);
        sB[2] = pack2(prB[4], prB[5]); sB[3] = pack2(prB[6], prB[7]);
        sB[4] = pack2(prB[8], 1.0f);
    }
}

extern "C" void kernel_launch(void* const* d_in, const int* in_sizes, int n_in,
                              void* d_out, int out_size)
{
    const float* src  = (const float*)d_in[0];
    const float* eWih = (const float*)d_in[1];
    const float* eWhh = (const float*)d_in[2];
    const float* eb   = (const float*)d_in[3];
    const float* dWih = (const float*)d_in[4];
    const float* dWhh = (const float*)d_in[5];
    const float* db   = (const float*)d_in[6];
    const float* fcW  = (const float*)d_in[7];
    const float* fcb  = (const float*)d_in[8];
    float* out = (float*)d_out;

    cudaFuncSetAttribute(lstm_seq2seq_kernel,
                         cudaFuncAttributeMaxDynamicSharedMemorySize, SMEM_BYTES);

    lstm_seq2seq_kernel<<<BTOT / EPB, TPB, SMEM_BYTES>>>(
        src, eWih, eWhh, eb, dWih, dWhh, db, fcW, fcb, out);
}